// round 14
// baseline (speedup 1.0000x reference)
#include <cuda_runtime.h>
#include <cuda_fp16.h>
#include <cstdint>
#include <math.h>

#define Bsz 16
#define Nn  256
#define Ll  64
#define Hh  32
#define HEe 128
#define EOo 64
#define LALPHA 0.2f

// ---------------- device scratch (no allocs allowed) ----------------
__device__ float g_h  [Bsz*Nn*Hh];
__device__ float g_mp [4][Bsz*Nn][EOo];                 // per-j-tile partial message sums
__device__ __align__(16) uint32_t g_rcvh[Bsz*Nn*64];    // fp16 k-pairs, permuted, be1 folded
__device__ __align__(16) uint32_t g_sndh[Bsz*Nn*64];    // fp16 k-pairs, permuted
__device__ __align__(16) uint4 g_Bfrag[3*1024];         // We2 fp16 fragment layout, 3 rounds

__device__ __forceinline__ float lrelu(float v) { return fmaxf(v, LALPHA * v); }
__device__ __forceinline__ __half2 u2h(uint32_t u) { return *(__half2*)&u; }
__device__ __forceinline__ uint32_t h2u(__half2 h) { return *(uint32_t*)&h; }
__device__ __forceinline__ int kslot(int c) { int kk = (2*c) & 15; return (c >> 3)*8 + (kk < 8 ? kk : kk - 7); }

// ---------------- K1: h0 init (coalesced, W_lin read once chip-wide) ----------------
__global__ void __launch_bounds__(256) k_init(const float* __restrict__ x,
                                              const float* __restrict__ W_lin,
                                              const float* __restrict__ b_lin,
                                              const float* __restrict__ W_in,
                                              const float* __restrict__ b_in) {
    __shared__ float xs[Bsz*Ll];
    __shared__ float ts[Bsz*256];
    __shared__ float Wins[Ll*Hh];
    __shared__ float bins[Hh];
    const int tid = threadIdx.x, ch = blockIdx.x;
    const int col = ch*256 + tid;

    for (int i = tid; i < Bsz*Ll; i += 256) xs[i] = x[i];
    for (int i = tid; i < Ll*Hh;  i += 256) Wins[i] = W_in[i];
    if (tid < Hh) bins[tid] = b_in[tid];
    __syncthreads();

    {
        float acc[Bsz];
        const float bl = b_lin[col];
        #pragma unroll
        for (int b = 0; b < Bsz; b++) acc[b] = bl;
        #pragma unroll 8
        for (int l2 = 0; l2 < Ll; l2++) {
            const float w = W_lin[(size_t)l2 * (Nn*Ll) + col];
            #pragma unroll
            for (int b = 0; b < Bsz; b++) acc[b] += xs[b*Ll + l2] * w;
        }
        #pragma unroll
        for (int b = 0; b < Bsz; b++) ts[b*256 + tid] = acc[b];
    }
    __syncthreads();

    {
        const int o = tid & 31, nd = (tid >> 5) & 3, bh = tid >> 7;
        #pragma unroll
        for (int bb = 0; bb < 8; bb++) {
            const int b = bh*8 + bb;
            float a = bins[o];
            #pragma unroll
            for (int c = 0; c < Ll; c++)
                a += ts[b*256 + nd*Ll + c] * Wins[c*Hh + o];
            g_h[((size_t)b*Nn + ch*4 + nd)*Hh + o] = a;
        }
    }
}

// ---------------- projection, 128 threads, 8 rows ----------------
__device__ __forceinline__ void project_rows8(const float* hs2,
                                              const float* __restrict__ We1_t,
                                              const float* __restrict__ be1_t,
                                              int base, int tid) {
    const int c = tid & 63, half = tid >> 6;
    const int slot = kslot(c);
    const float b0 = half ? 0.f : be1_t[2*c];
    const float b1 = half ? 0.f : be1_t[2*c + 1];
    uint32_t* dst = half ? g_sndh : g_rcvh;
    const float2* W2g = (const float2*)(We1_t + half*Hh*HEe);

    float2 wreg[Hh];
    #pragma unroll
    for (int hh = 0; hh < Hh; hh++) wreg[hh] = W2g[hh*64 + c];

    #pragma unroll
    for (int rp = 0; rp < 4; rp++) {
        const int r = rp*2;
        float a0 = b0, a1 = b1, a2 = b0, a3 = b1;
        #pragma unroll
        for (int hh = 0; hh < Hh; hh++) {
            const float hv0 = hs2[r*Hh + hh];
            const float hv1 = hs2[(r+1)*Hh + hh];
            a0 += hv0 * wreg[hh].x;
            a1 += hv0 * wreg[hh].y;
            a2 += hv1 * wreg[hh].x;
            a3 += hv1 * wreg[hh].y;
        }
        dst[(size_t)(base + r    )*64 + slot] = h2u(__floats2half2_rn(a0, a1));
        dst[(size_t)(base + r + 1)*64 + slot] = h2u(__floats2half2_rn(a2, a3));
    }
}

// ---------------- K2a: round-0 projections (8 rows/CTA) + We2 prep ----------------
__global__ void __launch_bounds__(128) k_rs0(const float* __restrict__ We1_t,
                                             const float* __restrict__ be1_t,
                                             const float* __restrict__ We2) {
    if (blockIdx.x >= 512) {
        const int t = blockIdx.x - 512, tid = threadIdx.x;
        const float* We2_t = We2 + (size_t)t * HEe * EOo;
        for (int e = tid; e < 1024; e += 128) {
            const int chunk = e >> 5, lane = e & 31;
            const int ks = chunk >> 2, ntp = chunk & 3;
            const int rr = lane >> 2,  q = lane & 3;
            const int k = ks*16 + 2*q;
            uint32_t bv[4];
            #pragma unroll
            for (int s = 0; s < 2; s++) {
                const int o = (2*ntp + s)*8 + rr;
                __half2 h0 = __floats2half2_rn(We2_t[k*EOo + o],     We2_t[(k+1)*EOo + o]);
                __half2 h1 = __floats2half2_rn(We2_t[(k+8)*EOo + o], We2_t[(k+9)*EOo + o]);
                bv[2*s]   = h2u(h0);
                bv[2*s+1] = h2u(h1);
            }
            g_Bfrag[t*1024 + e] = make_uint4(bv[0], bv[1], bv[2], bv[3]);
        }
        return;
    }
    __shared__ float hs[8*Hh];
    const int tid = threadIdx.x, base = blockIdx.x * 8;
    for (int i = tid; i < 8*Hh; i += 128) hs[i] = g_h[base*Hh + i];
    __syncthreads();
    project_rows8(hs, We1_t, be1_t, base, tid);
}

// ---------------- K4+K2 fused: node update + next-round projections ----------------
__global__ void __launch_bounds__(128) k_noders(const float* __restrict__ Wn0_t,
                                                const float* __restrict__ bn0_t,
                                                const float* __restrict__ Wn1_t,
                                                const float* __restrict__ bn1_t,
                                                const float* __restrict__ We1_n,
                                                const float* __restrict__ be1_n) {
    __shared__ float Wn0s[(Hh+EOo)*Hh];
    __shared__ float Wn1s[Hh*Hh];
    __shared__ float fs[8*96];
    __shared__ float n0s[8*Hh];
    __shared__ float hs2[8*Hh];
    const int tid = threadIdx.x, base = blockIdx.x * 8;

    for (int i = tid; i < (Hh+EOo)*Hh; i += 128) Wn0s[i] = Wn0_t[i];
    for (int i = tid; i < Hh*Hh;       i += 128) Wn1s[i] = Wn1_t[i];
    for (int i = tid; i < 8*Hh;        i += 128) fs[(i>>5)*96 + (i&31)] = g_h[base*Hh + i];
    for (int i = tid; i < 8*EOo;       i += 128) {
        const int r = i >> 6, o = i & 63;
        fs[r*96 + Hh + o] = g_mp[0][base+r][o] + g_mp[1][base+r][o]
                          + g_mp[2][base+r][o] + g_mp[3][base+r][o];
    }
    __syncthreads();

    const int o = tid & 31, rg = tid >> 5;
    const float bn0v = bn0_t[o], bn1v = bn1_t[o];

    {
        const int r0 = rg, r1 = rg + 4;
        float a0 = bn0v, a1 = bn0v;
        #pragma unroll
        for (int f = 0; f < Hh + EOo; f++) {
            const float wv = Wn0s[f*Hh + o];
            a0 += fs[r0*96 + f] * wv;
            a1 += fs[r1*96 + f] * wv;
        }
        n0s[r0*Hh + o] = lrelu(a0);
        n0s[r1*Hh + o] = lrelu(a1);
    }
    __syncthreads();
    {
        const int r0 = rg, r1 = rg + 4;
        float a0 = bn1v, a1 = bn1v;
        #pragma unroll
        for (int f = 0; f < Hh; f++) {
            const float wv = Wn1s[f*Hh + o];
            a0 += n0s[r0*Hh + f] * wv;
            a1 += n0s[r1*Hh + f] * wv;
        }
        const float h0 = lrelu(a0), h1 = lrelu(a1);
        hs2[r0*Hh + o] = h0;  g_h[(size_t)(base + r0)*Hh + o] = h0;
        hs2[r1*Hh + o] = h1;  g_h[(size_t)(base + r1)*Hh + o] = h1;
    }
    __syncthreads();
    project_rows8(hs2, We1_n, be1_n, base, tid);
}

// ---------------- K3: HMMA edge kernel — B in smem, 3 CTAs/SM ----------------
#define SND_HSTR 144
#define RCV_HSTR 144
// smem bytes: snd 18432 | rcv 9216 | be2 128 | Bs 8192
#define EDGE_SMEM (64*72*4 + 32*72*4 + 128 + 16*32*16)

__global__ void __launch_bounds__(256, 3) k_edge7(int t, const float* __restrict__ be2_t) {
    extern __shared__ __align__(16) unsigned char smraw[];
    uint32_t* snd_u = (uint32_t*)smraw;                         // [64][72]
    uint32_t* rcv_u = snd_u + 64*72;                            // [32][72]
    float*    be2s  = (float*)(rcv_u + 32*72);                  // [32] (+pad)
    uint4*    Bs    = (uint4*)(smraw + 64*72*4 + 32*72*4 + 128); // [16][32]

    const int tid = threadIdx.x, w = tid >> 5, lane = tid & 31;
    const int q = lane & 3, rr = lane >> 2;
    const int bix = blockIdx.x;
    const int oh = bix & 1, jt = (bix >> 1) & 3, it = (bix >> 3) & 7, b = bix >> 6;

    // ---- stage B fragments for this oh into smem (device-symbol indexed) ----
    {
        const uint4* Bf = g_Bfrag + t * 1024;
        #pragma unroll
        for (int p = tid; p < 512; p += 256) {
            const int chunk = p >> 5, ln = p & 31;           // chunk = ks*2 + s
            const int ks = chunk >> 1, s = chunk & 1;
            Bs[p] = Bf[(ks*4 + 2*oh + s)*32 + ln];
        }
    }
    // ---- stage tiles: pure uint4 copies (fp16, pre-permuted) ----
    {
        const uint4* sndg = (const uint4*)(g_sndh + (size_t)(b*Nn + jt*64)*64);
        #pragma unroll
        for (int p = tid; p < 1024; p += 256) {
            const int r = p >> 4, c = p & 15;
            *(uint4*)(snd_u + r*72 + c*4) = sndg[p];
        }
        const uint4* rcvg = (const uint4*)(g_rcvh + (size_t)(b*Nn + it*32)*64);
        #pragma unroll
        for (int p = tid; p < 512; p += 256) {
            const int r = p >> 4, c = p & 15;
            *(uint4*)(rcv_u + r*72 + c*4) = rcvg[p];
        }
    }
    if (tid < 32) be2s[tid] = be2_t[oh*32 + tid];
    __syncthreads();

    const __half2 alpha2 = __floats2half2_rn(LALPHA, LALPHA);
    const int q4 = q * 4;
    const __half* snd_sh = (const __half*)snd_u;
    const __half* rcv_sh = (const __half*)rcv_u;

    for (int ii = 0; ii < 4; ii++) {
        const int iloc = w*4 + ii;
        const __half* rcvp = &rcv_sh[iloc*RCV_HSTR + q4];

        float s[4][2];
        #pragma unroll
        for (int nt = 0; nt < 4; nt++) { s[nt][0] = 0.f; s[nt][1] = 0.f; }

        for (int mj = 0; mj < 4; mj++) {
            const __half* spA = &snd_sh[(mj*16 + rr)*SND_HSTR + q4];
            float acc[4][4];
            #pragma unroll
            for (int nt = 0; nt < 4; nt++)
                { acc[nt][0]=0.f; acc[nt][1]=0.f; acc[nt][2]=0.f; acc[nt][3]=0.f; }

            #pragma unroll
            for (int ks = 0; ks < 8; ks++) {
                const uint2 sa = *(const uint2*)(spA + ks*16);
                const uint2 sb = *(const uint2*)(spA + 8*SND_HSTR + ks*16);
                const uint2 rc = *(const uint2*)(rcvp + ks*16);
                const uint4 bb0 = Bs[(ks*2 + 0)*32 + lane];     // LDS.128, conflict-free
                const uint4 bb1 = Bs[(ks*2 + 1)*32 + lane];

                __half2 a0 = __hadd2(u2h(sa.x), u2h(rc.x));
                __half2 a1 = __hadd2(u2h(sb.x), u2h(rc.x));
                __half2 a2 = __hadd2(u2h(sa.y), u2h(rc.y));
                __half2 a3 = __hadd2(u2h(sb.y), u2h(rc.y));
                a0 = __hmax2(a0, __hmul2(a0, alpha2));
                a1 = __hmax2(a1, __hmul2(a1, alpha2));
                a2 = __hmax2(a2, __hmul2(a2, alpha2));
                a3 = __hmax2(a3, __hmul2(a3, alpha2));
                const uint32_t A0 = h2u(a0), A1 = h2u(a1), A2 = h2u(a2), A3 = h2u(a3);

                #pragma unroll
                for (int nt = 0; nt < 4; nt++) {
                    const uint4 bb = (nt < 2) ? bb0 : bb1;
                    const uint32_t b0 = (nt & 1) ? bb.z : bb.x;
                    const uint32_t b1 = (nt & 1) ? bb.w : bb.y;
                    asm volatile("mma.sync.aligned.m16n8k16.row.col.f32.f16.f16.f32 "
                                 "{%0,%1,%2,%3}, {%4,%5,%6,%7}, {%8,%9}, {%0,%1,%2,%3};"
                                 : "+f"(acc[nt][0]), "+f"(acc[nt][1]),
                                   "+f"(acc[nt][2]), "+f"(acc[nt][3])
                                 : "r"(A0), "r"(A1), "r"(A2), "r"(A3), "r"(b0), "r"(b1));
                }
            }

            #pragma unroll
            for (int nt = 0; nt < 4; nt++) {
                const float o0 = be2s[nt*8 + 2*q], o1 = be2s[nt*8 + 2*q + 1];
                s[nt][0] += lrelu(acc[nt][0] + o0) + lrelu(acc[nt][2] + o0);
                s[nt][1] += lrelu(acc[nt][1] + o1) + lrelu(acc[nt][3] + o1);
            }
        }

        #pragma unroll
        for (int nt = 0; nt < 4; nt++)
            #pragma unroll
            for (int e = 0; e < 2; e++) {
                float v = s[nt][e];
                v += __shfl_xor_sync(0xFFFFFFFFu, v, 4);
                v += __shfl_xor_sync(0xFFFFFFFFu, v, 8);
                v += __shfl_xor_sync(0xFFFFFFFFu, v, 16);
                s[nt][e] = v;
            }
        if (lane < 4) {
            const int row = b*Nn + it*32 + iloc;
            float* dst = &g_mp[jt][row][oh*32];
            #pragma unroll
            for (int nt = 0; nt < 4; nt++)
                *(float2*)&dst[nt*8 + 2*q] = make_float2(s[nt][0], s[nt][1]);
        }
    }
}

// ---------------- K4-final: node update + tanh output ----------------
__global__ void __launch_bounds__(256) k_nodef(const float* __restrict__ Wn0_t,
                                               const float* __restrict__ bn0_t,
                                               const float* __restrict__ Wn1_t,
                                               const float* __restrict__ bn1_t,
                                               float* __restrict__ out) {
    __shared__ float Wn0s[(Hh + EOo) * Hh];
    __shared__ float Wn1s[Hh * Hh];
    __shared__ float fs[8][Hh + EOo];
    __shared__ float n0s[8][Hh];
    const int tid = threadIdx.x, r = tid >> 5, o = tid & 31;
    const int row = blockIdx.x * 8 + r;

    for (int i = tid; i < (Hh + EOo) * Hh; i += 256) Wn0s[i] = Wn0_t[i];
    for (int i = tid; i < Hh * Hh;         i += 256) Wn1s[i] = Wn1_t[i];

    fs[r][o] = g_h[(size_t)row*Hh + o];
    {
        float m0 = 0.f, m1 = 0.f;
        #pragma unroll
        for (int jtt = 0; jtt < 4; jtt++) {
            m0 += g_mp[jtt][row][o];
            m1 += g_mp[jtt][row][Hh + o];
        }
        fs[r][Hh + o]      = m0;
        fs[r][Hh + Hh + o] = m1;
    }
    __syncthreads();

    float a = bn0_t[o];
    #pragma unroll
    for (int f = 0; f < Hh + EOo; f++) a += fs[r][f] * Wn0s[f*Hh + o];
    n0s[r][o] = lrelu(a);
    __syncthreads();

    float a2 = bn1_t[o];
    #pragma unroll
    for (int f = 0; f < Hh; f++) a2 += n0s[r][f] * Wn1s[f*Hh + o];
    out[(size_t)row*Hh + o] = tanhf(lrelu(a2));
}

// ---------------- launch ----------------
extern "C" void kernel_launch(void* const* d_in, const int* in_sizes, int n_in,
                              void* d_out, int out_size) {
    const float* x     = (const float*)d_in[0];
    const float* W_lin = (const float*)d_in[1];
    const float* b_lin = (const float*)d_in[2];
    const float* W_in  = (const float*)d_in[3];
    const float* b_in  = (const float*)d_in[4];
    const float* We1   = (const float*)d_in[5];
    const float* be1   = (const float*)d_in[6];
    const float* We2   = (const float*)d_in[7];
    const float* be2   = (const float*)d_in[8];
    const float* Wn0   = (const float*)d_in[9];
    const float* bn0   = (const float*)d_in[10];
    const float* Wn1   = (const float*)d_in[11];
    const float* bn1   = (const float*)d_in[12];
    float* out = (float*)d_out;

    cudaFuncSetAttribute(k_edge7, cudaFuncAttributeMaxDynamicSharedMemorySize, EDGE_SMEM);

    k_init<<<64, 256>>>(x, W_lin, b_lin, W_in, b_in);
    k_rs0<<<515, 128>>>(We1, be1, We2);
    for (int t = 0; t < 3; t++) {
        k_edge7<<<Bsz*8*4*2, 256, EDGE_SMEM>>>(t, be2 + t*EOo);
        if (t < 2) {
            k_noders<<<512, 128>>>(
                Wn0 + (size_t)t * (Hh+EOo)*Hh, bn0 + t*Hh,
                Wn1 + (size_t)t * Hh*Hh,        bn1 + t*Hh,
                We1 + (size_t)(t+1) * 2*Hh*HEe, be1 + (t+1)*HEe);
        } else {
            k_nodef<<<(Bsz*Nn)/8, 256>>>(
                Wn0 + (size_t)t * (Hh+EOo)*Hh, bn0 + t*Hh,
                Wn1 + (size_t)t * Hh*Hh,        bn1 + t*Hh, out);
        }
    }
}

// round 15
// speedup vs baseline: 1.1264x; 1.1264x over previous
#include <cuda_runtime.h>
#include <cuda_fp16.h>
#include <cstdint>
#include <math.h>

#define Bsz 16
#define Nn  256
#define Ll  64
#define Hh  32
#define HEe 128
#define EOo 64
#define LALPHA 0.2f

// ---------------- device scratch (no allocs allowed) ----------------
__device__ float g_h  [Bsz*Nn*Hh];
__device__ float g_mp [4][Bsz*Nn][EOo];                 // per-j-tile partial message sums
__device__ __align__(16) uint32_t g_rcvh[Bsz*Nn*64];    // fp16 k-pairs, permuted, be1 folded
__device__ __align__(16) uint32_t g_sndh[Bsz*Nn*64];    // fp16 k-pairs, permuted
__device__ __align__(16) uint4 g_Bfrag[3*1024];         // We2 fp16 fragment layout, 3 rounds

__device__ __forceinline__ float lrelu(float v) { return fmaxf(v, LALPHA * v); }
__device__ __forceinline__ __half2 u2h(uint32_t u) { return *(__half2*)&u; }
__device__ __forceinline__ uint32_t h2u(__half2 h) { return *(uint32_t*)&h; }
__device__ __forceinline__ int kslot(int c) { int kk = (2*c) & 15; return (c >> 3)*8 + (kk < 8 ? kk : kk - 7); }

// ---------------- K1: h0 init (coalesced, W_lin read once chip-wide) ----------------
__global__ void __launch_bounds__(256) k_init(const float* __restrict__ x,
                                              const float* __restrict__ W_lin,
                                              const float* __restrict__ b_lin,
                                              const float* __restrict__ W_in,
                                              const float* __restrict__ b_in) {
    __shared__ float xs[Bsz*Ll];
    __shared__ float ts[Bsz*256];
    __shared__ float Wins[Ll*Hh];
    __shared__ float bins[Hh];
    const int tid = threadIdx.x, ch = blockIdx.x;
    const int col = ch*256 + tid;

    for (int i = tid; i < Bsz*Ll; i += 256) xs[i] = x[i];
    for (int i = tid; i < Ll*Hh;  i += 256) Wins[i] = W_in[i];
    if (tid < Hh) bins[tid] = b_in[tid];
    __syncthreads();

    {
        float acc[Bsz];
        const float bl = b_lin[col];
        #pragma unroll
        for (int b = 0; b < Bsz; b++) acc[b] = bl;
        #pragma unroll 8
        for (int l2 = 0; l2 < Ll; l2++) {
            const float w = W_lin[(size_t)l2 * (Nn*Ll) + col];
            #pragma unroll
            for (int b = 0; b < Bsz; b++) acc[b] += xs[b*Ll + l2] * w;
        }
        #pragma unroll
        for (int b = 0; b < Bsz; b++) ts[b*256 + tid] = acc[b];
    }
    __syncthreads();

    {
        const int o = tid & 31, nd = (tid >> 5) & 3, bh = tid >> 7;
        #pragma unroll
        for (int bb = 0; bb < 8; bb++) {
            const int b = bh*8 + bb;
            float a = bins[o];
            #pragma unroll
            for (int c = 0; c < Ll; c++)
                a += ts[b*256 + nd*Ll + c] * Wins[c*Hh + o];
            g_h[((size_t)b*Nn + ch*4 + nd)*Hh + o] = a;
        }
    }
}

// ---------------- projection, 128 threads, 8 rows ----------------
__device__ __forceinline__ void project_rows8(const float* hs2,
                                              const float* __restrict__ We1_t,
                                              const float* __restrict__ be1_t,
                                              int base, int tid) {
    const int c = tid & 63, half = tid >> 6;
    const int slot = kslot(c);
    const float b0 = half ? 0.f : be1_t[2*c];
    const float b1 = half ? 0.f : be1_t[2*c + 1];
    uint32_t* dst = half ? g_sndh : g_rcvh;
    const float2* W2g = (const float2*)(We1_t + half*Hh*HEe);

    float2 wreg[Hh];
    #pragma unroll
    for (int hh = 0; hh < Hh; hh++) wreg[hh] = W2g[hh*64 + c];

    #pragma unroll
    for (int rp = 0; rp < 4; rp++) {
        const int r = rp*2;
        float a0 = b0, a1 = b1, a2 = b0, a3 = b1;
        #pragma unroll
        for (int hh = 0; hh < Hh; hh++) {
            const float hv0 = hs2[r*Hh + hh];
            const float hv1 = hs2[(r+1)*Hh + hh];
            a0 += hv0 * wreg[hh].x;
            a1 += hv0 * wreg[hh].y;
            a2 += hv1 * wreg[hh].x;
            a3 += hv1 * wreg[hh].y;
        }
        dst[(size_t)(base + r    )*64 + slot] = h2u(__floats2half2_rn(a0, a1));
        dst[(size_t)(base + r + 1)*64 + slot] = h2u(__floats2half2_rn(a2, a3));
    }
}

// ---------------- K2a: round-0 projections (8 rows/CTA) + We2 prep ----------------
__global__ void __launch_bounds__(128) k_rs0(const float* __restrict__ We1_t,
                                             const float* __restrict__ be1_t,
                                             const float* __restrict__ We2) {
    if (blockIdx.x >= 512) {
        const int t = blockIdx.x - 512, tid = threadIdx.x;
        const float* We2_t = We2 + (size_t)t * HEe * EOo;
        for (int e = tid; e < 1024; e += 128) {
            const int chunk = e >> 5, lane = e & 31;
            const int ks = chunk >> 2, ntp = chunk & 3;
            const int rr = lane >> 2,  q = lane & 3;
            const int k = ks*16 + 2*q;
            uint32_t bv[4];
            #pragma unroll
            for (int s = 0; s < 2; s++) {
                const int o = (2*ntp + s)*8 + rr;
                __half2 h0 = __floats2half2_rn(We2_t[k*EOo + o],     We2_t[(k+1)*EOo + o]);
                __half2 h1 = __floats2half2_rn(We2_t[(k+8)*EOo + o], We2_t[(k+9)*EOo + o]);
                bv[2*s]   = h2u(h0);
                bv[2*s+1] = h2u(h1);
            }
            g_Bfrag[t*1024 + e] = make_uint4(bv[0], bv[1], bv[2], bv[3]);
        }
        return;
    }
    __shared__ float hs[8*Hh];
    const int tid = threadIdx.x, base = blockIdx.x * 8;
    for (int i = tid; i < 8*Hh; i += 128) hs[i] = g_h[base*Hh + i];
    __syncthreads();
    project_rows8(hs, We1_t, be1_t, base, tid);
}

// ---------------- K4+K2 fused: node update + next-round projections ----------------
__global__ void __launch_bounds__(128) k_noders(const float* __restrict__ Wn0_t,
                                                const float* __restrict__ bn0_t,
                                                const float* __restrict__ Wn1_t,
                                                const float* __restrict__ bn1_t,
                                                const float* __restrict__ We1_n,
                                                const float* __restrict__ be1_n) {
    __shared__ float Wn0s[(Hh+EOo)*Hh];
    __shared__ float Wn1s[Hh*Hh];
    __shared__ float fs[8*96];
    __shared__ float n0s[8*Hh];
    __shared__ float hs2[8*Hh];
    const int tid = threadIdx.x, base = blockIdx.x * 8;

    for (int i = tid; i < (Hh+EOo)*Hh; i += 128) Wn0s[i] = Wn0_t[i];
    for (int i = tid; i < Hh*Hh;       i += 128) Wn1s[i] = Wn1_t[i];
    for (int i = tid; i < 8*Hh;        i += 128) fs[(i>>5)*96 + (i&31)] = g_h[base*Hh + i];
    for (int i = tid; i < 8*EOo;       i += 128) {
        const int r = i >> 6, o = i & 63;
        fs[r*96 + Hh + o] = g_mp[0][base+r][o] + g_mp[1][base+r][o]
                          + g_mp[2][base+r][o] + g_mp[3][base+r][o];
    }
    __syncthreads();

    const int o = tid & 31, rg = tid >> 5;
    const float bn0v = bn0_t[o], bn1v = bn1_t[o];

    {
        const int r0 = rg, r1 = rg + 4;
        float a0 = bn0v, a1 = bn0v;
        #pragma unroll
        for (int f = 0; f < Hh + EOo; f++) {
            const float wv = Wn0s[f*Hh + o];
            a0 += fs[r0*96 + f] * wv;
            a1 += fs[r1*96 + f] * wv;
        }
        n0s[r0*Hh + o] = lrelu(a0);
        n0s[r1*Hh + o] = lrelu(a1);
    }
    __syncthreads();
    {
        const int r0 = rg, r1 = rg + 4;
        float a0 = bn1v, a1 = bn1v;
        #pragma unroll
        for (int f = 0; f < Hh; f++) {
            const float wv = Wn1s[f*Hh + o];
            a0 += n0s[r0*Hh + f] * wv;
            a1 += n0s[r1*Hh + f] * wv;
        }
        const float h0 = lrelu(a0), h1 = lrelu(a1);
        hs2[r0*Hh + o] = h0;  g_h[(size_t)(base + r0)*Hh + o] = h0;
        hs2[r1*Hh + o] = h1;  g_h[(size_t)(base + r1)*Hh + o] = h1;
    }
    __syncthreads();
    project_rows8(hs2, We1_n, be1_n, base, tid);
}

// ---------------- K3: HMMA edge kernel (R13 version — B in registers) ----------------
#define SND_HSTR 144
#define RCV_HSTR 144
#define EDGE_SMEM (64*72*4 + 32*72*4 + 32*4)

__global__ void __launch_bounds__(256, 2) k_edge6(int t, const float* __restrict__ be2_t) {
    extern __shared__ __align__(16) unsigned char smraw[];
    uint32_t* snd_u = (uint32_t*)smraw;
    uint32_t* rcv_u = snd_u + 64*72;
    float*    be2s  = (float*)(rcv_u + 32*72);

    const int tid = threadIdx.x, w = tid >> 5, lane = tid & 31;
    const int q = lane & 3, rr = lane >> 2;
    const int bix = blockIdx.x;
    const int oh = bix & 1, jt = (bix >> 1) & 3, it = (bix >> 3) & 7, b = bix >> 6;

    const uint4* Bf = g_Bfrag + t * 1024;
    uint4 breg[16];
    #pragma unroll
    for (int ks = 0; ks < 8; ks++) {
        breg[ks*2 + 0] = Bf[(ks*4 + 2*oh + 0)*32 + lane];
        breg[ks*2 + 1] = Bf[(ks*4 + 2*oh + 1)*32 + lane];
    }

    {
        const uint4* sndg = (const uint4*)(g_sndh + (size_t)(b*Nn + jt*64)*64);
        #pragma unroll
        for (int p = tid; p < 1024; p += 256) {
            const int r = p >> 4, c = p & 15;
            *(uint4*)(snd_u + r*72 + c*4) = sndg[p];
        }
        const uint4* rcvg = (const uint4*)(g_rcvh + (size_t)(b*Nn + it*32)*64);
        #pragma unroll
        for (int p = tid; p < 512; p += 256) {
            const int r = p >> 4, c = p & 15;
            *(uint4*)(rcv_u + r*72 + c*4) = rcvg[p];
        }
    }
    if (tid < 32) be2s[tid] = be2_t[oh*32 + tid];
    __syncthreads();

    const __half2 alpha2 = __floats2half2_rn(LALPHA, LALPHA);
    const int q4 = q * 4;
    const __half* snd_sh = (const __half*)snd_u;
    const __half* rcv_sh = (const __half*)rcv_u;

    for (int ii = 0; ii < 4; ii++) {
        const int iloc = w*4 + ii;
        const __half* rcvp = &rcv_sh[iloc*RCV_HSTR + q4];

        float s[4][2];
        #pragma unroll
        for (int nt = 0; nt < 4; nt++) { s[nt][0] = 0.f; s[nt][1] = 0.f; }

        for (int mj = 0; mj < 4; mj++) {
            const __half* spA = &snd_sh[(mj*16 + rr)*SND_HSTR + q4];
            float acc[4][4];
            #pragma unroll
            for (int nt = 0; nt < 4; nt++)
                { acc[nt][0]=0.f; acc[nt][1]=0.f; acc[nt][2]=0.f; acc[nt][3]=0.f; }

            #pragma unroll
            for (int ks = 0; ks < 8; ks++) {
                const uint2 sa = *(const uint2*)(spA + ks*16);
                const uint2 sb = *(const uint2*)(spA + 8*SND_HSTR + ks*16);
                const uint2 rc = *(const uint2*)(rcvp + ks*16);

                __half2 a0 = __hadd2(u2h(sa.x), u2h(rc.x));
                __half2 a1 = __hadd2(u2h(sb.x), u2h(rc.x));
                __half2 a2 = __hadd2(u2h(sa.y), u2h(rc.y));
                __half2 a3 = __hadd2(u2h(sb.y), u2h(rc.y));
                a0 = __hmax2(a0, __hmul2(a0, alpha2));
                a1 = __hmax2(a1, __hmul2(a1, alpha2));
                a2 = __hmax2(a2, __hmul2(a2, alpha2));
                a3 = __hmax2(a3, __hmul2(a3, alpha2));
                const uint32_t A0 = h2u(a0), A1 = h2u(a1), A2 = h2u(a2), A3 = h2u(a3);

                #pragma unroll
                for (int nt = 0; nt < 4; nt++) {
                    const uint4 bb = breg[ks*2 + (nt >> 1)];
                    const uint32_t b0 = (nt & 1) ? bb.z : bb.x;
                    const uint32_t b1 = (nt & 1) ? bb.w : bb.y;
                    asm volatile("mma.sync.aligned.m16n8k16.row.col.f32.f16.f16.f32 "
                                 "{%0,%1,%2,%3}, {%4,%5,%6,%7}, {%8,%9}, {%0,%1,%2,%3};"
                                 : "+f"(acc[nt][0]), "+f"(acc[nt][1]),
                                   "+f"(acc[nt][2]), "+f"(acc[nt][3])
                                 : "r"(A0), "r"(A1), "r"(A2), "r"(A3), "r"(b0), "r"(b1));
                }
            }

            #pragma unroll
            for (int nt = 0; nt < 4; nt++) {
                const float o0 = be2s[nt*8 + 2*q], o1 = be2s[nt*8 + 2*q + 1];
                s[nt][0] += lrelu(acc[nt][0] + o0) + lrelu(acc[nt][2] + o0);
                s[nt][1] += lrelu(acc[nt][1] + o1) + lrelu(acc[nt][3] + o1);
            }
        }

        #pragma unroll
        for (int nt = 0; nt < 4; nt++)
            #pragma unroll
            for (int e = 0; e < 2; e++) {
                float v = s[nt][e];
                v += __shfl_xor_sync(0xFFFFFFFFu, v, 4);
                v += __shfl_xor_sync(0xFFFFFFFFu, v, 8);
                v += __shfl_xor_sync(0xFFFFFFFFu, v, 16);
                s[nt][e] = v;
            }
        if (lane < 4) {
            const int row = b*Nn + it*32 + iloc;
            float* dst = &g_mp[jt][row][oh*32];
            #pragma unroll
            for (int nt = 0; nt < 4; nt++)
                *(float2*)&dst[nt*8 + 2*q] = make_float2(s[nt][0], s[nt][1]);
        }
    }
}

// ---------------- K4-final: node update + tanh (k_noders shape, no projection) ----------------
__global__ void __launch_bounds__(128) k_nodef(const float* __restrict__ Wn0_t,
                                               const float* __restrict__ bn0_t,
                                               const float* __restrict__ Wn1_t,
                                               const float* __restrict__ bn1_t,
                                               float* __restrict__ out) {
    __shared__ float Wn0s[(Hh+EOo)*Hh];
    __shared__ float Wn1s[Hh*Hh];
    __shared__ float fs[8*96];
    __shared__ float n0s[8*Hh];
    const int tid = threadIdx.x, base = blockIdx.x * 8;

    for (int i = tid; i < (Hh+EOo)*Hh; i += 128) Wn0s[i] = Wn0_t[i];
    for (int i = tid; i < Hh*Hh;       i += 128) Wn1s[i] = Wn1_t[i];
    for (int i = tid; i < 8*Hh;        i += 128) fs[(i>>5)*96 + (i&31)] = g_h[base*Hh + i];
    for (int i = tid; i < 8*EOo;       i += 128) {
        const int r = i >> 6, o = i & 63;
        fs[r*96 + Hh + o] = g_mp[0][base+r][o] + g_mp[1][base+r][o]
                          + g_mp[2][base+r][o] + g_mp[3][base+r][o];
    }
    __syncthreads();

    const int o = tid & 31, rg = tid >> 5;
    const float bn0v = bn0_t[o], bn1v = bn1_t[o];

    {
        const int r0 = rg, r1 = rg + 4;
        float a0 = bn0v, a1 = bn0v;
        #pragma unroll
        for (int f = 0; f < Hh + EOo; f++) {
            const float wv = Wn0s[f*Hh + o];
            a0 += fs[r0*96 + f] * wv;
            a1 += fs[r1*96 + f] * wv;
        }
        n0s[r0*Hh + o] = lrelu(a0);
        n0s[r1*Hh + o] = lrelu(a1);
    }
    __syncthreads();
    {
        const int r0 = rg, r1 = rg + 4;
        float a0 = bn1v, a1 = bn1v;
        #pragma unroll
        for (int f = 0; f < Hh; f++) {
            const float wv = Wn1s[f*Hh + o];
            a0 += n0s[r0*Hh + f] * wv;
            a1 += n0s[r1*Hh + f] * wv;
        }
        out[(size_t)(base + r0)*Hh + o] = tanhf(lrelu(a0));
        out[(size_t)(base + r1)*Hh + o] = tanhf(lrelu(a1));
    }
}

// ---------------- launch ----------------
extern "C" void kernel_launch(void* const* d_in, const int* in_sizes, int n_in,
                              void* d_out, int out_size) {
    const float* x     = (const float*)d_in[0];
    const float* W_lin = (const float*)d_in[1];
    const float* b_lin = (const float*)d_in[2];
    const float* W_in  = (const float*)d_in[3];
    const float* b_in  = (const float*)d_in[4];
    const float* We1   = (const float*)d_in[5];
    const float* be1   = (const float*)d_in[6];
    const float* We2   = (const float*)d_in[7];
    const float* be2   = (const float*)d_in[8];
    const float* Wn0   = (const float*)d_in[9];
    const float* bn0   = (const float*)d_in[10];
    const float* Wn1   = (const float*)d_in[11];
    const float* bn1   = (const float*)d_in[12];
    float* out = (float*)d_out;

    cudaFuncSetAttribute(k_edge6, cudaFuncAttributeMaxDynamicSharedMemorySize, EDGE_SMEM);

    k_init<<<64, 256>>>(x, W_lin, b_lin, W_in, b_in);
    k_rs0<<<515, 128>>>(We1, be1, We2);
    for (int t = 0; t < 3; t++) {
        k_edge6<<<Bsz*8*4*2, 256, EDGE_SMEM>>>(t, be2 + t*EOo);
        if (t < 2) {
            k_noders<<<512, 128>>>(
                Wn0 + (size_t)t * (Hh+EOo)*Hh, bn0 + t*Hh,
                Wn1 + (size_t)t * Hh*Hh,        bn1 + t*Hh,
                We1 + (size_t)(t+1) * 2*Hh*HEe, be1 + (t+1)*HEe);
        } else {
            k_nodef<<<512, 128>>>(
                Wn0 + (size_t)t * (Hh+EOo)*Hh, bn0 + t*Hh,
                Wn1 + (size_t)t * Hh*Hh,        bn1 + t*Hh, out);
        }
    }
}